// round 9
// baseline (speedup 1.0000x reference)
#include <cuda_runtime.h>
#include <math.h>
#include <stdint.h>

// Problem constants
#define BB    8
#define CC    128
#define NN    65536
#define NOBJ  64

#define PBLK     512               // points per stage-1 block (chunk)
#define HT       32                // points per tile (128B rows)
#define NHT      (PBLK / HT)       // 16 tiles
#define THREADS1 512               // 16 warps; warp w owns segs 4w..4w+3
#define NWARP    16
#define NCHUNK   (NN / PBLK)       // 128
#define NCID     (BB * NCHUNK)     // 1024 chunks
#define NBUCK    (NWARP * NHT)     // 256 buckets per chunk
#define TILE_W   (HT * CC)         // 4096 words per tile

// Scratch (static device array: allowed)
__device__ float g_partial[(size_t)NCID * NOBJ * CC];   // 32 MB

// ---- cp.async helpers (4-byte variant enables 4B-granular swizzles) --------
__device__ __forceinline__ void cp_async4(uint32_t dst, const void* src) {
    asm volatile("cp.async.ca.shared.global [%0], [%1], 4;\n" :: "r"(dst), "l"(src));
}
__device__ __forceinline__ void cp_commit() { asm volatile("cp.async.commit_group;\n"); }
template <int N> __device__ __forceinline__ void cp_wait() {
    asm volatile("cp.async.wait_group %0;\n" :: "n"(N));
}

// ---------------------------------------------------------------------------
// Stage 1 (prep fused): per-(batch, 512-point chunk) segment max.
//
//  LOADS: cp.async 4B, channel-major tile with 4B XOR swizzle
//         word(c, pt) = c*32 + (pt ^ (c & 31)).
//         gmem: warp op = 32 consecutive points of one channel row -> 1 line
//               group, fully coalesced.
//         smem write: banks = pt ^ (c&31) -> permutation -> conflict-free.
//  SORT (fused prep): block-local counting sort of its 512 points into
//         256 buckets (owner_warp = s>>2, tile = pt>>5); entry = pt|(s&3)<<9.
//         Runs while the first two tile prefetches are in flight.
//         Intra-bucket order is atomic-race nondeterministic, but max() is
//         commutative -> output deterministic.
//  COMPUTE: warp w owns segs 4w..4w+3; lane owns chans {l,l+32,l+64,l+96};
//         16 register accumulators, predicated FMAX.
//         gather: v_k = tb[lane*32 + k*1024 + (pt^lane)] -> bank permutation
//         -> conflict-free: 5 wavefronts/entry (was 17 with 16B swizzle).
//  Drain rule: wait_group 1 except final tile (wait_group 0).
// ---------------------------------------------------------------------------
__global__ __launch_bounds__(THREADS1) void seg_max_stage1(
    const float* __restrict__ feat, const int* __restrict__ idx32)
{
    __shared__ float buf[2][TILE_W];            // 2 x 16 KB
    __shared__ int   Psm[NBUCK + 1];
    __shared__ int   pos[NBUCK];                // hist, then scatter cursor
    __shared__ unsigned short Esm[PBLK];
    __shared__ int   ok;
    __shared__ int   wsum[8];

    const int tid  = threadIdx.x;
    const int lane = tid & 31;
    const int w    = tid >> 5;
    const int cid  = blockIdx.x;
    const float* fbase = feat + (size_t)(cid >> 7) * CC * NN + (cid & 127) * PBLK;

    const uint32_t buf_u = (uint32_t)__cvta_generic_to_shared(&buf[0][0]);

    // ---- issue tile 0,1 prefetches first (latency hidden behind the sort) --
    auto prefetch = [&](int t) {
        const uint32_t base = buf_u + (uint32_t)((t & 1) * TILE_W * 4);
        const float* sb = fbase + t * HT;
        #pragma unroll
        for (int k = 0; k < 8; ++k) {
            int i  = tid + k * THREADS1;        // 0..4095
            int c  = i >> 5;
            int pt = i & 31;
            cp_async4(base + (uint32_t)((c * 32 + (pt ^ (c & 31))) * 4),
                      sb + (size_t)c * NN + pt);
        }
        cp_commit();
    };
    prefetch(0);
    prefetch(1);

    // ---- fused prep: dtype probe + block-local counting sort ---------------
    if (tid == 0) ok = 1;
    if (tid < NBUCK) pos[tid] = 0;
    __syncthreads();
    if (tid < 256) {
        // int64 in [0,64) -> int32 view [v,0,...]; random int32 cannot keep
        // all 256 odd words zero. Reads words 0..511: safe under either dtype.
        int lo = idx32[2 * tid];
        int hi = idx32[2 * tid + 1];
        if (hi != 0 || lo < 0 || lo >= NOBJ) atomicAnd(&ok, 0);
    }
    __syncthreads();
    const int s = idx32[(size_t)(cid * PBLK + tid) * (ok ? 2 : 1)];
    const int bucket = (s >> 2) * NHT + (tid >> 5);
    atomicAdd(&pos[bucket], 1);
    __syncthreads();

    if (tid < NBUCK) {           // exclusive scan of 256 counts
        int v = pos[tid];
        int inc = v;
        #pragma unroll
        for (int d = 1; d < 32; d <<= 1) {
            int t = __shfl_up_sync(0xffffffffu, inc, d);
            if (lane >= d) inc += t;
        }
        if (lane == 31) wsum[w] = inc;
        __syncthreads();
        if (tid == 0) {
            int run = 0;
            #pragma unroll
            for (int i = 0; i < 8; ++i) { int t = wsum[i]; wsum[i] = run; run += t; }
        }
        __syncthreads();
        int exc = inc - v + wsum[w];
        Psm[tid] = exc;
        pos[tid] = exc;
        if (tid == 0) Psm[NBUCK] = PBLK;
    } else {
        __syncthreads();
        __syncthreads();
    }
    __syncthreads();
    {
        int r = atomicAdd(&pos[bucket], 1);
        Esm[r] = (unsigned short)(tid | ((s & 3) << 9));
    }
    // (visibility of Esm/Psm is covered by the barrier at top of tile loop)

    float r0[4], r1[4], r2[4], r3[4];
    #pragma unroll
    for (int k = 0; k < 4; ++k) {
        r0[k] = -INFINITY; r1[k] = -INFINITY;
        r2[k] = -INFINITY; r3[k] = -INFINITY;
    }

    for (int t = 0; t < NHT; ++t) {
        if (t < NHT - 1) cp_wait<1>(); else cp_wait<0>();
        __syncthreads();                         // tile t + sort results visible

        const float* tb = buf[t & 1];
        const int i0 = Psm[w * NHT + t];
        const int i1 = Psm[w * NHT + t + 1];
        for (int i = i0; i < i1; ++i) {          // warp-uniform walk
            const unsigned e  = Esm[i];          // broadcast
            const int lp = e & 31;               // local point in tile
            const int sl = (e >> 9) & 3;         // warp-uniform 0..3
            const int a  = lane * 32 + (lp ^ lane);
            float v0 = tb[a];
            float v1 = tb[a + 1024];
            float v2 = tb[a + 2048];
            float v3 = tb[a + 3072];
            r0[0] = (sl == 0) ? fmaxf(r0[0], v0) : r0[0];
            r0[1] = (sl == 0) ? fmaxf(r0[1], v1) : r0[1];
            r0[2] = (sl == 0) ? fmaxf(r0[2], v2) : r0[2];
            r0[3] = (sl == 0) ? fmaxf(r0[3], v3) : r0[3];
            r1[0] = (sl == 1) ? fmaxf(r1[0], v0) : r1[0];
            r1[1] = (sl == 1) ? fmaxf(r1[1], v1) : r1[1];
            r1[2] = (sl == 1) ? fmaxf(r1[2], v2) : r1[2];
            r1[3] = (sl == 1) ? fmaxf(r1[3], v3) : r1[3];
            r2[0] = (sl == 2) ? fmaxf(r2[0], v0) : r2[0];
            r2[1] = (sl == 2) ? fmaxf(r2[1], v1) : r2[1];
            r2[2] = (sl == 2) ? fmaxf(r2[2], v2) : r2[2];
            r2[3] = (sl == 2) ? fmaxf(r2[3], v3) : r2[3];
            r3[0] = (sl == 3) ? fmaxf(r3[0], v0) : r3[0];
            r3[1] = (sl == 3) ? fmaxf(r3[1], v1) : r3[1];
            r3[2] = (sl == 3) ? fmaxf(r3[2], v2) : r3[2];
            r3[3] = (sl == 3) ? fmaxf(r3[3], v3) : r3[3];
        }
        __syncthreads();                         // buffer fully consumed
        if (t + 2 < NHT) prefetch(t + 2);
    }

    // Writeout: 128B-coalesced per (seg, k-group) row segment.
    float* outp = g_partial + (size_t)cid * (NOBJ * CC) + (4 * w) * CC + lane;
    #pragma unroll
    for (int k = 0; k < 4; ++k) {
        outp[0 * CC + 32 * k] = r0[k];
        outp[1 * CC + 32 * k] = r1[k];
        outp[2 * CC + 32 * k] = r2[k];
        outp[3 * CC + 32 * k] = r3[k];
    }
}

// ---------------------------------------------------------------------------
// Stage 2: reduce 128 per-chunk partials per (b, seg, c-quad); -inf -> 0.
// ---------------------------------------------------------------------------
__global__ void seg_max_stage2(float* __restrict__ out) {
    int o4 = blockIdx.x * blockDim.x + threadIdx.x;   // 0..16383 float4s
    int c4 = o4 & (CC / 4 - 1);
    int g  = o4 >> 5;
    int b  = g >> 6;
    int s  = g & (NOBJ - 1);

    const float4* __restrict__ p =
        (const float4*)(g_partial + (size_t)b * NCHUNK * (NOBJ * CC) + s * CC) + c4;

    float4 m = make_float4(-INFINITY, -INFINITY, -INFINITY, -INFINITY);
    #pragma unroll 4
    for (int k = 0; k < NCHUNK; ++k) {
        float4 v = p[(size_t)k * (NOBJ * CC / 4)];
        m.x = fmaxf(m.x, v.x); m.y = fmaxf(m.y, v.y);
        m.z = fmaxf(m.z, v.z); m.w = fmaxf(m.w, v.w);
    }
    float4 r;
    r.x = isfinite(m.x) ? m.x : 0.0f;
    r.y = isfinite(m.y) ? m.y : 0.0f;
    r.z = isfinite(m.z) ? m.z : 0.0f;
    r.w = isfinite(m.w) ? m.w : 0.0f;
    ((float4*)out)[o4] = r;
}

// ---------------------------------------------------------------------------
extern "C" void kernel_launch(void* const* d_in, const int* in_sizes, int n_in,
                              void* d_out, int out_size)
{
    const float* feat = nullptr;
    const int*   idx  = nullptr;
    for (int i = 0; i < n_in; ++i) {
        if (in_sizes[i] == BB * CC * NN)  feat = (const float*)d_in[i];
        else if (in_sizes[i] == BB * NN)  idx  = (const int*)d_in[i];
    }

    seg_max_stage1<<<NCID, THREADS1>>>(feat, idx);
    seg_max_stage2<<<(BB * NOBJ * CC / 4) / 256, 256>>>((float*)d_out);
}

// round 10
// speedup vs baseline: 1.2343x; 1.2343x over previous
#include <cuda_runtime.h>
#include <math.h>
#include <stdint.h>

// Problem constants
#define BB    8
#define CC    128
#define NN    65536
#define NOBJ  64

#define PBLK     1024              // points per stage-1 block (chunk)
#define HT       32                // points per tile (128B rows)
#define NHT      (PBLK / HT)       // 32 tiles
#define THREADS1 512               // 16 warps; warp w owns segs 4w..4w+3
#define NWARP    16
#define NCHUNK   (NN / PBLK)       // 64
#define NCID     (BB * NCHUNK)     // 512 chunks
#define NBUCK    (NWARP * NHT)     // 512 buckets per chunk == THREADS1
#define TILE_W   (HT * CC)         // 4096 words per tile

// Scratch (static device array: allowed)
__device__ float g_partial[(size_t)NCID * NOBJ * CC];   // 16 MB (L2-resident)

// ---- cp.async helpers (16B: measured-best load path, rounds 4/6) -----------
__device__ __forceinline__ void cp_async16(uint32_t dst, const void* src) {
    asm volatile("cp.async.cg.shared.global [%0], [%1], 16;\n" :: "r"(dst), "l"(src));
}
__device__ __forceinline__ void cp_commit() { asm volatile("cp.async.commit_group;\n"); }
template <int N> __device__ __forceinline__ void cp_wait() {
    asm volatile("cp.async.wait_group %0;\n" :: "n"(N));
}

// ---------------------------------------------------------------------------
// Stage 1 (prep fused): per-(batch, 1024-point chunk) segment max.
//   LOADS: cp.async 16B, channel-major tile [128c][32pt], 16B-granule swizzle
//          word(c, g) = c*32 + ((g ^ (c&7))<<2); coalesced gmem (4 lines/op).
//   SORT (fused): block-local counting sort of 1024 points into 512 buckets
//          (owner_warp = s>>2, tile = pt>>5); entry = pt | (s&3)<<10.
//          Runs while the first two tile prefetches are in flight. Intra-
//          bucket order is nondeterministic but max() is commutative.
//   COMPUTE: warp w owns segs 4w..4w+3; lane owns chans {l,l+32,l+64,l+96};
//          16 register accumulators, predicated FMAX; gather 4-way conflicted
//          (measured cheaper than conflict-free alternatives).
//   Drain: wait_group 1 except final tile (wait_group 0).
// ---------------------------------------------------------------------------
__global__ __launch_bounds__(THREADS1) void seg_max_stage1(
    const float* __restrict__ feat, const int* __restrict__ idx32)
{
    __shared__ float buf[2][TILE_W];            // 2 x 16 KB
    __shared__ int   Psm[NBUCK + 1];
    __shared__ int   pos[NBUCK];                // hist, then scatter cursor
    __shared__ unsigned short Esm[PBLK];        // 2 KB
    __shared__ int   ok;
    __shared__ int   wsum[NWARP];

    const int tid  = threadIdx.x;
    const int lane = tid & 31;
    const int w    = tid >> 5;
    const int cid  = blockIdx.x;
    const float* fbase = feat + (size_t)(cid >> 6) * CC * NN + (cid & 63) * PBLK;

    const uint32_t buf_u = (uint32_t)__cvta_generic_to_shared(&buf[0][0]);

    auto prefetch = [&](int t) {
        const uint32_t base = buf_u + (uint32_t)((t & 1) * TILE_W * 4);
        const float* sb = fbase + t * HT;
        #pragma unroll
        for (int k = 0; k < 2; ++k) {
            int i = tid + k * THREADS1;          // 0..1023 16B slots
            int c = i >> 3;                      // channel row 0..127
            int g = i & 7;                       // 16B granule in row
            cp_async16(base + (uint32_t)((c * 32 + ((g ^ (c & 7)) << 2)) * 4),
                       sb + (size_t)c * NN + g * 4);
        }
        cp_commit();
    };
    prefetch(0);
    prefetch(1);

    // ---- fused prep: dtype probe + block-local counting sort ---------------
    if (tid == 0) ok = 1;
    pos[tid] = 0;
    __syncthreads();
    if (tid < 256) {
        // int64 in [0,64) -> int32 view [v,0,...]; random int32 cannot keep
        // all 256 odd words zero. Reads words 0..511: safe under either dtype.
        int lo = idx32[2 * tid];
        int hi = idx32[2 * tid + 1];
        if (hi != 0 || lo < 0 || lo >= NOBJ) atomicAnd(&ok, 0);
    }
    __syncthreads();
    const int stride = ok ? 2 : 1;
    const int p0 = tid, p1 = tid + THREADS1;
    const int s0 = idx32[(size_t)(cid * PBLK + p0) * stride];
    const int s1 = idx32[(size_t)(cid * PBLK + p1) * stride];
    const int b0 = (s0 >> 2) * NHT + (p0 >> 5);
    const int b1 = (s1 >> 2) * NHT + (p1 >> 5);
    atomicAdd(&pos[b0], 1);
    atomicAdd(&pos[b1], 1);
    __syncthreads();

    {   // exclusive scan over 512 counts (1 per thread)
        int v = pos[tid];
        int inc = v;
        #pragma unroll
        for (int d = 1; d < 32; d <<= 1) {
            int t = __shfl_up_sync(0xffffffffu, inc, d);
            if (lane >= d) inc += t;
        }
        if (lane == 31) wsum[w] = inc;
        __syncthreads();
        if (tid == 0) {
            int run = 0;
            #pragma unroll
            for (int i = 0; i < NWARP; ++i) { int t = wsum[i]; wsum[i] = run; run += t; }
        }
        __syncthreads();
        int exc = inc - v + wsum[w];
        Psm[tid] = exc;
        pos[tid] = exc;
        if (tid == 0) Psm[NBUCK] = PBLK;
    }
    __syncthreads();
    {
        int r = atomicAdd(&pos[b0], 1);
        Esm[r] = (unsigned short)(p0 | ((s0 & 3) << 10));
        r = atomicAdd(&pos[b1], 1);
        Esm[r] = (unsigned short)(p1 | ((s1 & 3) << 10));
    }
    // Esm/Psm visibility: barrier at top of tile loop.

    float r0[4], r1[4], r2[4], r3[4];
    #pragma unroll
    for (int k = 0; k < 4; ++k) {
        r0[k] = -INFINITY; r1[k] = -INFINITY;
        r2[k] = -INFINITY; r3[k] = -INFINITY;
    }

    for (int t = 0; t < NHT; ++t) {
        if (t < NHT - 1) cp_wait<1>(); else cp_wait<0>();
        __syncthreads();                         // tile t + sort results visible

        const float* tb = buf[t & 1];
        const int i0 = Psm[w * NHT + t];
        const int i1 = Psm[w * NHT + t + 1];
        for (int i = i0; i < i1; ++i) {          // warp-uniform walk
            const unsigned e  = Esm[i];          // broadcast
            const int lp = e & 31;               // local point in tile
            const int sl = (e >> 10) & 3;        // warp-uniform 0..3
            const int a  = lane * 32 + (((lp >> 2) ^ (lane & 7)) << 2) + (lp & 3);
            float v0 = tb[a];
            float v1 = tb[a + 1024];
            float v2 = tb[a + 2048];
            float v3 = tb[a + 3072];
            r0[0] = (sl == 0) ? fmaxf(r0[0], v0) : r0[0];
            r0[1] = (sl == 0) ? fmaxf(r0[1], v1) : r0[1];
            r0[2] = (sl == 0) ? fmaxf(r0[2], v2) : r0[2];
            r0[3] = (sl == 0) ? fmaxf(r0[3], v3) : r0[3];
            r1[0] = (sl == 1) ? fmaxf(r1[0], v0) : r1[0];
            r1[1] = (sl == 1) ? fmaxf(r1[1], v1) : r1[1];
            r1[2] = (sl == 1) ? fmaxf(r1[2], v2) : r1[2];
            r1[3] = (sl == 1) ? fmaxf(r1[3], v3) : r1[3];
            r2[0] = (sl == 2) ? fmaxf(r2[0], v0) : r2[0];
            r2[1] = (sl == 2) ? fmaxf(r2[1], v1) : r2[1];
            r2[2] = (sl == 2) ? fmaxf(r2[2], v2) : r2[2];
            r2[3] = (sl == 2) ? fmaxf(r2[3], v3) : r2[3];
            r3[0] = (sl == 3) ? fmaxf(r3[0], v0) : r3[0];
            r3[1] = (sl == 3) ? fmaxf(r3[1], v1) : r3[1];
            r3[2] = (sl == 3) ? fmaxf(r3[2], v2) : r3[2];
            r3[3] = (sl == 3) ? fmaxf(r3[3], v3) : r3[3];
        }
        __syncthreads();                         // buffer fully consumed
        if (t + 2 < NHT) prefetch(t + 2);
    }

    // Writeout: 128B-coalesced per (seg, k-group) row segment.
    float* outp = g_partial + (size_t)cid * (NOBJ * CC) + (4 * w) * CC + lane;
    #pragma unroll
    for (int k = 0; k < 4; ++k) {
        outp[0 * CC + 32 * k] = r0[k];
        outp[1 * CC + 32 * k] = r1[k];
        outp[2 * CC + 32 * k] = r2[k];
        outp[3 * CC + 32 * k] = r3[k];
    }
}

// ---------------------------------------------------------------------------
// Stage 2: block per (b, seg) = 512 blocks x 128 threads (one per channel).
// Coalesced 512B row reads, 64-chunk unrolled max; -inf -> 0 guard.
// 16 MB of partials, freshly written -> mostly L2 hits.
// ---------------------------------------------------------------------------
__global__ __launch_bounds__(CC) void seg_max_stage2(float* __restrict__ out) {
    const int c  = threadIdx.x;
    const int g  = blockIdx.x;        // b*NOBJ + s
    const int b  = g >> 6;
    const int s  = g & (NOBJ - 1);

    const float* __restrict__ p =
        g_partial + (size_t)b * NCHUNK * (NOBJ * CC) + s * CC + c;

    float m = -INFINITY;
    #pragma unroll 8
    for (int k = 0; k < NCHUNK; ++k)
        m = fmaxf(m, p[(size_t)k * (NOBJ * CC)]);

    out[g * CC + c] = isfinite(m) ? m : 0.0f;
}

// ---------------------------------------------------------------------------
extern "C" void kernel_launch(void* const* d_in, const int* in_sizes, int n_in,
                              void* d_out, int out_size)
{
    const float* feat = nullptr;
    const int*   idx  = nullptr;
    for (int i = 0; i < n_in; ++i) {
        if (in_sizes[i] == BB * CC * NN)  feat = (const float*)d_in[i];
        else if (in_sizes[i] == BB * NN)  idx  = (const int*)d_in[i];
    }

    seg_max_stage1<<<NCID, THREADS1>>>(feat, idx);
    seg_max_stage2<<<BB * NOBJ, CC>>>((float*)d_out);
}

// round 11
// speedup vs baseline: 1.2868x; 1.0426x over previous
#include <cuda_runtime.h>
#include <math.h>
#include <stdint.h>

// Problem constants
#define BB    8
#define CC    128
#define NN    65536
#define NOBJ  64

#define PBLK     512               // points per stage-1 block (chunk)
#define HT       32                // points per tile (128B rows)
#define NHT      (PBLK / HT)       // 16 tiles
#define DEPTH    3                 // pipeline depth (triple buffer)
#define THREADS1 512               // 16 warps; warp w owns segs 4w..4w+3
#define NWARP    16
#define NCHUNK   (NN / PBLK)       // 128
#define NCID     (BB * NCHUNK)     // 1024 chunks
#define NBUCK    (NWARP * NHT)     // 256 buckets per chunk
#define TILE_W   (HT * CC)         // 4096 words per tile
#define OUTN     (BB * NOBJ * CC)  // 65536 outputs

// Global accumulator (float bit patterns), L2-resident 256 KB.
__device__ int g_acc[OUTN];

// ---- cp.async helpers -------------------------------------------------------
__device__ __forceinline__ void cp_async16(uint32_t dst, const void* src) {
    asm volatile("cp.async.cg.shared.global [%0], [%1], 16;\n" :: "r"(dst), "l"(src));
}
__device__ __forceinline__ void cp_commit() { asm volatile("cp.async.commit_group;\n"); }
template <int N> __device__ __forceinline__ void cp_wait() {
    asm volatile("cp.async.wait_group %0;\n" :: "n"(N));
}

// Monotone float-max join on a global int-pattern cell. Both branches only
// move the stored value UP in float order -> commutative, associative,
// deterministic under any interleaving. Init must be 0xFF800000 (-inf).
__device__ __forceinline__ void atomic_fmax(int* a, float v) {
    if (v >= 0.0f) atomicMax(a, __float_as_int(v));
    else           atomicMin((unsigned int*)a, (unsigned int)__float_as_int(v));
}

// ---------------------------------------------------------------------------
__global__ void init_acc() {
    g_acc[blockIdx.x * 512 + threadIdx.x] = 0xFF800000;   // -inf pattern
}

// ---------------------------------------------------------------------------
// Stage 1 (prep fused): per-(batch, 512-point chunk) segment max.
//   LOADS: cp.async 16B, channel-major tile [128c][32pt], 16B-granule swizzle
//          word(c,g) = c*32 + ((g ^ (c&7))<<2); coalesced gmem (4 lines/op);
//          triple-buffered (depth 3) for DRAM MLP.
//   SORT (fused): block-local counting sort of 512 points into 256 buckets
//          (owner_warp = s>>2, tile = pt>>5); entry = pt | (s&3)<<9.
//          Runs while the first three tile prefetches are in flight.
//   COMPUTE: warp w owns segs 4w..4w+3; lane owns chans {l,l+32,l+64,l+96};
//          16 register accumulators, predicated FMAX.
//   OUTPUT: 16 atomic_fmax per thread straight into g_acc (no partials,
//          no stage-2 reduction kernel).
//   Drain: group t must be complete at iter t -> wait_group min(2, NHT-1-t).
// ---------------------------------------------------------------------------
extern __shared__ float dynbuf[];     // [DEPTH][TILE_W] = 48 KB

__global__ __launch_bounds__(THREADS1) void seg_max_stage1(
    const float* __restrict__ feat, const int* __restrict__ idx32)
{
    __shared__ int   Psm[NBUCK + 1];
    __shared__ int   pos[NBUCK];                // hist, then scatter cursor
    __shared__ unsigned short Esm[PBLK];        // 1 KB
    __shared__ int   ok;
    __shared__ int   wsum[8];

    const int tid  = threadIdx.x;
    const int lane = tid & 31;
    const int w    = tid >> 5;
    const int cid  = blockIdx.x;
    const float* fbase = feat + (size_t)(cid >> 7) * CC * NN + (cid & 127) * PBLK;

    const uint32_t buf_u = (uint32_t)__cvta_generic_to_shared(dynbuf);

    auto prefetch = [&](int t) {
        const uint32_t base = buf_u + (uint32_t)((t % DEPTH) * TILE_W * 4);
        const float* sb = fbase + t * HT;
        #pragma unroll
        for (int k = 0; k < 2; ++k) {
            int i = tid + k * THREADS1;          // 0..1023 16B slots
            int c = i >> 3;                      // channel row 0..127
            int g = i & 7;                       // 16B granule in row
            cp_async16(base + (uint32_t)((c * 32 + ((g ^ (c & 7)) << 2)) * 4),
                       sb + (size_t)c * NN + g * 4);
        }
        cp_commit();
    };
    prefetch(0);
    prefetch(1);
    prefetch(2);

    // ---- fused prep: dtype probe + block-local counting sort ---------------
    if (tid == 0) ok = 1;
    if (tid < NBUCK) pos[tid] = 0;
    __syncthreads();
    if (tid < 256) {
        // int64 in [0,64) -> int32 view [v,0,...]; random int32 cannot keep
        // all 256 odd words zero. Reads words 0..511: safe under either dtype.
        int lo = idx32[2 * tid];
        int hi = idx32[2 * tid + 1];
        if (hi != 0 || lo < 0 || lo >= NOBJ) atomicAnd(&ok, 0);
    }
    __syncthreads();
    const int s = idx32[(size_t)(cid * PBLK + tid) * (ok ? 2 : 1)];
    const int bucket = (s >> 2) * NHT + (tid >> 5);
    atomicAdd(&pos[bucket], 1);
    __syncthreads();

    int v = 0, inc = 0;
    if (tid < NBUCK) {            // warp-scan of 256 counts (warps 0..7 whole)
        v = pos[tid];
        inc = v;
        #pragma unroll
        for (int d = 1; d < 32; d <<= 1) {
            int t = __shfl_up_sync(0xffffffffu, inc, d);
            if (lane >= d) inc += t;
        }
        if (lane == 31) wsum[w] = inc;
    }
    __syncthreads();
    if (tid == 0) {
        int run = 0;
        #pragma unroll
        for (int i = 0; i < 8; ++i) { int t = wsum[i]; wsum[i] = run; run += t; }
    }
    __syncthreads();
    if (tid < NBUCK) {
        int exc = inc - v + wsum[w];
        Psm[tid] = exc;
        pos[tid] = exc;
    }
    if (tid == 0) Psm[NBUCK] = PBLK;
    __syncthreads();
    {
        int r = atomicAdd(&pos[bucket], 1);
        Esm[r] = (unsigned short)(tid | ((s & 3) << 9));
    }
    // Esm/Psm visibility: barrier at top of tile loop.

    float r0[4], r1[4], r2[4], r3[4];
    #pragma unroll
    for (int k = 0; k < 4; ++k) {
        r0[k] = -INFINITY; r1[k] = -INFINITY;
        r2[k] = -INFINITY; r3[k] = -INFINITY;
    }

    for (int t = 0; t < NHT; ++t) {
        if      (t < NHT - 2) cp_wait<2>();
        else if (t < NHT - 1) cp_wait<1>();
        else                  cp_wait<0>();
        __syncthreads();                         // tile t + sort results visible

        const float* tb = dynbuf + (t % DEPTH) * TILE_W;
        const int i0 = Psm[w * NHT + t];
        const int i1 = Psm[w * NHT + t + 1];
        for (int i = i0; i < i1; ++i) {          // warp-uniform walk
            const unsigned e  = Esm[i];          // broadcast
            const int lp = e & 31;               // local point in tile
            const int sl = (e >> 9) & 3;         // warp-uniform 0..3
            const int a  = lane * 32 + (((lp >> 2) ^ (lane & 7)) << 2) + (lp & 3);
            float v0 = tb[a];
            float v1 = tb[a + 1024];
            float v2 = tb[a + 2048];
            float v3 = tb[a + 3072];
            r0[0] = (sl == 0) ? fmaxf(r0[0], v0) : r0[0];
            r0[1] = (sl == 0) ? fmaxf(r0[1], v1) : r0[1];
            r0[2] = (sl == 0) ? fmaxf(r0[2], v2) : r0[2];
            r0[3] = (sl == 0) ? fmaxf(r0[3], v3) : r0[3];
            r1[0] = (sl == 1) ? fmaxf(r1[0], v0) : r1[0];
            r1[1] = (sl == 1) ? fmaxf(r1[1], v1) : r1[1];
            r1[2] = (sl == 1) ? fmaxf(r1[2], v2) : r1[2];
            r1[3] = (sl == 1) ? fmaxf(r1[3], v3) : r1[3];
            r2[0] = (sl == 2) ? fmaxf(r2[0], v0) : r2[0];
            r2[1] = (sl == 2) ? fmaxf(r2[1], v1) : r2[1];
            r2[2] = (sl == 2) ? fmaxf(r2[2], v2) : r2[2];
            r2[3] = (sl == 2) ? fmaxf(r2[3], v3) : r2[3];
            r3[0] = (sl == 3) ? fmaxf(r3[0], v0) : r3[0];
            r3[1] = (sl == 3) ? fmaxf(r3[1], v1) : r3[1];
            r3[2] = (sl == 3) ? fmaxf(r3[2], v2) : r3[2];
            r3[3] = (sl == 3) ? fmaxf(r3[3], v3) : r3[3];
        }
        __syncthreads();                         // buffer fully consumed
        if (t + DEPTH < NHT) prefetch(t + DEPTH);
    }

    // Fold accumulators straight into the global joint max (deterministic).
    int* accp = g_acc + ((cid >> 7) * NOBJ + 4 * w) * CC + lane;
    #pragma unroll
    for (int k = 0; k < 4; ++k) {
        atomic_fmax(accp + 0 * CC + 32 * k, r0[k]);
        atomic_fmax(accp + 1 * CC + 32 * k, r1[k]);
        atomic_fmax(accp + 2 * CC + 32 * k, r2[k]);
        atomic_fmax(accp + 3 * CC + 32 * k, r3[k]);
    }
}

// ---------------------------------------------------------------------------
// Finalize: pattern -> float, -inf (empty segment) -> 0 guard.
// ---------------------------------------------------------------------------
__global__ void finalize_acc(float* __restrict__ out) {
    int i = blockIdx.x * 512 + threadIdx.x;
    float f = __int_as_float(g_acc[i]);
    out[i] = isfinite(f) ? f : 0.0f;
}

// ---------------------------------------------------------------------------
extern "C" void kernel_launch(void* const* d_in, const int* in_sizes, int n_in,
                              void* d_out, int out_size)
{
    const float* feat = nullptr;
    const int*   idx  = nullptr;
    for (int i = 0; i < n_in; ++i) {
        if (in_sizes[i] == BB * CC * NN)  feat = (const float*)d_in[i];
        else if (in_sizes[i] == BB * NN)  idx  = (const int*)d_in[i];
    }

    const int dyn = DEPTH * TILE_W * 4;          // 48 KB
    static int attr_set = 0;
    if (!attr_set) {
        cudaFuncSetAttribute(seg_max_stage1,
                             cudaFuncAttributeMaxDynamicSharedMemorySize, dyn);
        attr_set = 1;
    }

    init_acc<<<OUTN / 512, 512>>>();
    seg_max_stage1<<<NCID, THREADS1, dyn>>>(feat, idx);
    finalize_acc<<<OUTN / 512, 512>>>((float*)d_out);
}